// round 7
// baseline (speedup 1.0000x reference)
#include <cuda_runtime.h>
#include <math_constants.h>
#include <cstdint>

#define BS 8
#define NQ 1000
#define D 256
#define NROWS (BS * NQ)
#define TOPK 10
#define MAX_PAIRS (NROWS * TOPK)
#define MROWS 10      // rows per block in mask kernel
#define GROUP 32      // rows/pairs per group in MMA kernels
#define XSTR 260      // floats per X row in shared (unsplit, 256 + 4 pad)
#define WSTR 520      // floats per Ws k-row (256 cols as hi,lo pairs + 8 pad)
#define KC 16         // k-chunk for W staging
#define GRID_MMA 444
#define SMEM_MMA ((GROUP * XSTR + KC * WSTR) * 4)   // 66,560 bytes

// ---------------- scratch (no allocations allowed) ----------------
__device__ float g_P[NROWS * D];      // P = id_token @ W3 (active rows only)
__device__ float g_cur[NROWS * D];    // running max of masked features (active rows only)
__device__ int   g_pairs[MAX_PAIRS * 2];
__device__ int   g_pair_count;
__device__ int   g_flag[NROWS];
__device__ int   g_idrows[NROWS];
__device__ int   g_nid;
__device__ int   g_outrows[NROWS];
__device__ int   g_nout;

__global__ void k_reset() {
    const int i = blockIdx.x * 256 + threadIdx.x;
    if (i < NROWS) g_flag[i] = 0;
    if (i == 0) { g_pair_count = 0; g_nid = 0; g_nout = 0; }
}

__device__ __forceinline__ void atomicMaxFloat(float* addr, float v) {
    if (v >= 0.0f) atomicMax((int*)addr, __float_as_int(v));
    else           atomicMin((unsigned int*)addr, __float_as_uint(v));
}

// ---------------- tf32 split helpers (3xTF32 scheme) ----------------
__device__ __forceinline__ void split_tf32(float x, float& hi, float& lo) {
    asm("cvt.rna.tf32.f32 %0, %1;" : "=f"(hi) : "f"(x));
    lo = x - hi;   // exact
}
__device__ __forceinline__ void split4_store(float* dst, float4 v) {
    float h0,l0,h1,l1,h2,l2,h3,l3;
    split_tf32(v.x,h0,l0); split_tf32(v.y,h1,l1);
    split_tf32(v.z,h2,l2); split_tf32(v.w,h3,l3);
    *(float4*)(dst)     = make_float4(h0,l0,h1,l1);
    *(float4*)(dst + 4) = make_float4(h2,l2,h3,l3);
}

__device__ __forceinline__ void mma_tf32(float c[4],
    uint32_t a0, uint32_t a1, uint32_t a2, uint32_t a3,
    uint32_t b0, uint32_t b1)
{
    asm volatile(
        "mma.sync.aligned.m16n8k8.row.col.f32.tf32.tf32.f32 "
        "{%0,%1,%2,%3}, {%4,%5,%6,%7}, {%8,%9}, {%0,%1,%2,%3};"
        : "+f"(c[0]), "+f"(c[1]), "+f"(c[2]), "+f"(c[3])
        : "r"(a0), "r"(a1), "r"(a2), "r"(a3), "r"(b0), "r"(b1));
}

// Core: C[8][4] = Xs(32 x D, unsplit) @ Wg(D x D), 3xTF32.
// Warp (rg,cg): rows rg*16..+15, cols cg*64..+63 (8 n-tiles of 8).
// Xs rows unsplit (split in regs at A-load); W staged to Ws as (hi,lo) pairs.
__device__ __forceinline__ void mma_layer(
    const float* Xs, float* Ws, const float* __restrict__ Wg,
    float C[8][4], int rg, int cg, int g, int tig, int t)
{
#pragma unroll
    for (int nt = 0; nt < 8; nt++)
#pragma unroll
        for (int i = 0; i < 4; i++) C[nt][i] = 0.0f;

    const int row0 = rg * 16 + g;

    for (int kc = 0; kc < D; kc += KC) {
        __syncthreads();   // Ws free (first iter also orders Xs writes)
        // stage W[kc..kc+16)[0..256) as (hi,lo) pairs: 1024 float4 over 256 thr
#pragma unroll
        for (int i = 0; i < 4; i++) {
            const int idx = t + (i << 8);
            const int k  = idx >> 6;
            const int c4 = (idx & 63) << 2;
            const float4 w = *(const float4*)(Wg + (size_t)(kc + k) * D + c4);
            split4_store(Ws + k * WSTR + (c4 << 1), w);
        }
        __syncthreads();
#pragma unroll
        for (int ks = 0; ks < KC; ks += 8) {
            const int kk = kc + ks + tig;
            const float a0f = Xs[row0 * XSTR + kk];
            const float a1f = Xs[(row0 + 8) * XSTR + kk];
            const float a2f = Xs[row0 * XSTR + kk + 4];
            const float a3f = Xs[(row0 + 8) * XSTR + kk + 4];
            float a0h,a0l,a1h,a1l,a2h,a2l,a3h,a3l;
            split_tf32(a0f,a0h,a0l); split_tf32(a1f,a1h,a1l);
            split_tf32(a2f,a2h,a2l); split_tf32(a3f,a3h,a3l);
            const uint32_t A0h=__float_as_uint(a0h), A0l=__float_as_uint(a0l);
            const uint32_t A1h=__float_as_uint(a1h), A1l=__float_as_uint(a1l);
            const uint32_t A2h=__float_as_uint(a2h), A2l=__float_as_uint(a2l);
            const uint32_t A3h=__float_as_uint(a3h), A3l=__float_as_uint(a3l);
#pragma unroll
            for (int nt = 0; nt < 8; nt++) {
                const int col = cg * 64 + nt * 8 + g;
                const float2 b0 = *(const float2*)(Ws + (ks + tig) * WSTR + (col << 1));
                const float2 b1 = *(const float2*)(Ws + (ks + tig + 4) * WSTR + (col << 1));
                const uint32_t B0h=__float_as_uint(b0.x), B0l=__float_as_uint(b0.y);
                const uint32_t B1h=__float_as_uint(b1.x), B1l=__float_as_uint(b1.y);
                mma_tf32(C[nt], A0h,A1h,A2h,A3h, B0h, B1h);
                mma_tf32(C[nt], A0h,A1h,A2h,A3h, B0l, B1l);
                mma_tf32(C[nt], A0l,A1l,A2l,A3l, B0h, B1h);
            }
        }
    }
}

// ---------------- K2: IoU mask + selection + cur-init + base output ----------------
__global__ __launch_bounds__(256) void k_mask_sel(
    const float* __restrict__ pred, const float* __restrict__ seed,
    const float* __restrict__ tgt,  const float* __restrict__ b5,
    float* __restrict__ out, float* __restrict__ out_mask)
{
    const int base = blockIdx.x * MROWS;
    const int b = base / NQ;
    const int t = threadIdx.x;

    __shared__ float4 s_box[NQ];
    __shared__ float  s_seed[NQ];
    __shared__ int    s_cnt, s_m;
    __shared__ float  sval[256];
    __shared__ int    sidx[256];

    const float rb5 = fmaxf(b5[t], 0.0f);

    for (int j = t; j < NQ; j += 256) {
        s_box[j]  = ((const float4*)pred)[b * NQ + j];
        s_seed[j] = seed[b * NQ + j];
    }
    __syncthreads();

    for (int r = 0; r < MROWS; r++) {
        const int row = base + r;
        const int li  = row - b * NQ;
        if (t == 0) s_cnt = 0;
        __syncthreads();

        const float4 pb = s_box[li];
        const float bx1 = __fsub_rn(pb.x, __fmul_rn(0.5f, pb.z));
        const float by1 = __fsub_rn(pb.y, __fmul_rn(0.5f, pb.w));
        const float bx2 = __fadd_rn(pb.x, __fmul_rn(0.5f, pb.z));
        const float by2 = __fadd_rn(pb.y, __fmul_rn(0.5f, pb.w));
        const float ai  = __fmul_rn(__fsub_rn(bx2, bx1), __fsub_rn(by2, by1));
        const bool negi = (s_seed[li] == 0.0f);

        for (int j = t; j < NQ; j += 256) {
            const float4 q = s_box[j];
            const float qx1 = __fsub_rn(q.x, __fmul_rn(0.5f, q.z));
            const float qy1 = __fsub_rn(q.y, __fmul_rn(0.5f, q.w));
            const float qx2 = __fadd_rn(q.x, __fmul_rn(0.5f, q.z));
            const float qy2 = __fadd_rn(q.y, __fmul_rn(0.5f, q.w));
            const float aj  = __fmul_rn(__fsub_rn(qx2, qx1), __fsub_rn(qy2, qy1));
            const float w = fmaxf(__fsub_rn(fminf(bx2, qx2), fmaxf(bx1, qx1)), 0.0f);
            const float h = fmaxf(__fsub_rn(fminf(by2, qy2), fmaxf(by1, qy1)), 0.0f);
            const float inter = __fmul_rn(w, h);
            const float uni = __fsub_rn(__fadd_rn(ai, aj), inter);
            const float iou = __fdiv_rn(inter, uni);
            const bool attn = (iou >= 0.5f);
            out_mask[(size_t)row * NQ + j] = attn ? 1.0f : 0.0f;
            if (attn && negi && (s_seed[j] != 0.0f)) {
                int p = atomicAdd(&s_cnt, 1);
                if (p < 256) { sval[p] = iou; sidx[p] = j; }
            }
        }
        __syncthreads();

        if (t == 0) {
            int cnt = min(s_cnt, 256);
            int m;
            int sel[TOPK];
            if (cnt <= TOPK) {
                m = cnt;
                for (int qq = 0; qq < cnt; qq++) sel[qq] = sidx[qq];
            } else {
                m = TOPK;
                for (int rr = 0; rr < TOPK; rr++) {
                    float best = -1.0f; int bj = 0x7fffffff; int bp = -1;
                    for (int p = 0; p < cnt; p++) {
                        float v = sval[p]; int j = sidx[p];
                        if (v > best || (v == best && j < bj)) { best = v; bj = j; bp = p; }
                    }
                    sel[rr] = bj;
                    sval[bp] = -1.0f;
                }
            }
            s_m = m;
            if (m > 0) {
                int pbase = atomicAdd(&g_pair_count, m);
                for (int qq = 0; qq < m; qq++) {
                    g_pairs[2 * (pbase + qq)]     = row;
                    g_pairs[2 * (pbase + qq) + 1] = sel[qq];
                    g_flag[b * NQ + sel[qq]] = 1;
                }
                g_flag[row] = 1;
                int op = atomicAdd(&g_nout, 1);
                g_outrows[op] = row;
            }
        }
        __syncthreads();
        const int m = s_m;
        if (m == 0) {
            const float neg = 1.0f - s_seed[li];
            out[(size_t)row * D + t] = tgt[(size_t)row * D + t] + rb5 * neg;
        } else {
            g_cur[(size_t)row * D + t] = (m < TOPK) ? 0.0f : -CUDART_INF_F;
        }
    }
}

// ---------------- compaction of id-rows ----------------
__global__ void k_compact() {
    const int i = blockIdx.x * 256 + threadIdx.x;
    if (i < NROWS && g_flag[i]) {
        int p = atomicAdd(&g_nid, 1);
        g_idrows[p] = i;
    }
}

// ---------------- K3: P = (LN(relu(tgt@W1+b1)@W2+b2)*g2+be2) @ W3 ----------------
__global__ __launch_bounds__(256, 3) void k_idtoken(
    const float* __restrict__ tgt,
    const float* __restrict__ W1, const float* __restrict__ b1,
    const float* __restrict__ W2, const float* __restrict__ b2,
    const float* __restrict__ g2, const float* __restrict__ be2,
    const float* __restrict__ W3)
{
    extern __shared__ float sm[];
    float* Xs = sm;                       // GROUP * XSTR (unsplit)
    float* Ws = sm + GROUP * XSTR;        // KC * WSTR (split pairs)
    __shared__ int   srow[GROUP];
    __shared__ float s_mean[GROUP], s_rstd[GROUP];

    const int t = threadIdx.x;
    const int w = t >> 5, lane = t & 31;
    const int rg = w & 1, cg = w >> 1;
    const int g = lane >> 2, tig = lane & 3;
    const int nact = g_nid;

    const float gv = g2[t], bev = be2[t];

    for (int g0 = blockIdx.x * GROUP; g0 < nact; g0 += gridDim.x * GROUP) {
        if (t < GROUP) srow[t] = (g0 + t < nact) ? g_idrows[g0 + t] : -1;
        __syncthreads();

        // stage X = tgt rows (unsplit): 2048 float4 over 256 threads
#pragma unroll
        for (int i = 0; i < 8; i++) {
            const int idx = t + (i << 8);
            const int r = idx >> 6, c4 = (idx & 63) << 2;
            const int rr = srow[r];
            const float4 v = (rr >= 0) ? *(const float4*)(tgt + (size_t)rr * D + c4)
                                       : make_float4(0.f, 0.f, 0.f, 0.f);
            *(float4*)(Xs + r * XSTR + c4) = v;
        }

        float C[8][4];
        // layer 1
        mma_layer(Xs, Ws, W1, C, rg, cg, g, tig, t);
        __syncthreads();
#pragma unroll
        for (int nt = 0; nt < 8; nt++) {
            const int col = cg * 64 + nt * 8 + (tig << 1);
            const float2 bb = *(const float2*)(b1 + col);
            const int r0 = rg * 16 + g, r1 = r0 + 8;
            *(float2*)(Xs + r0 * XSTR + col) =
                make_float2(fmaxf(C[nt][0] + bb.x, 0.f), fmaxf(C[nt][1] + bb.y, 0.f));
            *(float2*)(Xs + r1 * XSTR + col) =
                make_float2(fmaxf(C[nt][2] + bb.x, 0.f), fmaxf(C[nt][3] + bb.y, 0.f));
        }

        // layer 2 (pre-LN z)
        mma_layer(Xs, Ws, W2, C, rg, cg, g, tig, t);
        __syncthreads();
#pragma unroll
        for (int nt = 0; nt < 8; nt++) {
            const int col = cg * 64 + nt * 8 + (tig << 1);
            const float2 bb = *(const float2*)(b2 + col);
            const int r0 = rg * 16 + g, r1 = r0 + 8;
            *(float2*)(Xs + r0 * XSTR + col) = make_float2(C[nt][0] + bb.x, C[nt][1] + bb.y);
            *(float2*)(Xs + r1 * XSTR + col) = make_float2(C[nt][2] + bb.x, C[nt][3] + bb.y);
        }
        __syncthreads();

        // LN stats: warp w handles rows 4w..4w+3
        for (int rr = (w << 2); rr < (w << 2) + 4; rr++) {
            float s = 0.f, sq = 0.f;
            for (int c = lane; c < D; c += 32) {
                const float z = Xs[rr * XSTR + c];
                s += z; sq += z * z;
            }
#pragma unroll
            for (int off = 16; off > 0; off >>= 1) {
                s  += __shfl_down_sync(0xffffffff, s,  off);
                sq += __shfl_down_sync(0xffffffff, sq, off);
            }
            if (lane == 0) {
                const float m = s * (1.0f / D);
                s_mean[rr] = m;
                s_rstd[rr] = rsqrtf(sq * (1.0f / D) - m * m + 1e-5f);
            }
        }
        __syncthreads();

        // LN transform: thread t = col t, loop rows
#pragma unroll 4
        for (int r = 0; r < GROUP; r++) {
            const float z = Xs[r * XSTR + t];
            Xs[r * XSTR + t] = (z - s_mean[r]) * s_rstd[r] * gv + bev;
        }

        // layer 3: P = id @ W3 (b3 applied at pair stage)
        mma_layer(Xs, Ws, W3, C, rg, cg, g, tig, t);
#pragma unroll
        for (int nt = 0; nt < 8; nt++) {
            const int col = cg * 64 + nt * 8 + (tig << 1);
            const int r0 = rg * 16 + g, r1 = r0 + 8;
            const int rw0 = srow[r0], rw1 = srow[r1];
            if (rw0 >= 0)
                *(float2*)(g_P + (size_t)rw0 * D + col) = make_float2(C[nt][0], C[nt][1]);
            if (rw1 >= 0)
                *(float2*)(g_P + (size_t)rw1 * D + col) = make_float2(C[nt][2], C[nt][3]);
        }
        __syncthreads();
    }
}

// ---------------- K4a: per-pair relu(P_i - P_j + b3) @ W4 + b4 -> seg-max + atomic ----------------
__global__ __launch_bounds__(256, 3) void k_feat(
    const float* __restrict__ b3,
    const float* __restrict__ W4, const float* __restrict__ b4)
{
    extern __shared__ float sm[];
    float* Xs = sm;
    float* Ws = sm + GROUP * XSTR;
    __shared__ int spr[GROUP], sjj[GROUP];

    const int t = threadIdx.x;
    const int w = t >> 5, lane = t & 31;
    const int rg = w & 1, cg = w >> 1;
    const int g = lane >> 2, tig = lane & 3;
    const int npairs = g_pair_count;

    const float bias4 = b4[t];

    for (int g0 = blockIdx.x * GROUP; g0 < npairs; g0 += gridDim.x * GROUP) {
        if (t < GROUP) {
            if (g0 + t < npairs) {
                spr[t] = g_pairs[2 * (g0 + t)];
                sjj[t] = g_pairs[2 * (g0 + t) + 1];
            } else spr[t] = -1;
        }
        __syncthreads();

        // stage X = relu(P_i - P_j + b3) (unsplit)
#pragma unroll
        for (int i = 0; i < 8; i++) {
            const int idx = t + (i << 8);
            const int p = idx >> 6, c4 = (idx & 63) << 2;
            const int rp = spr[p];
            float4 v = make_float4(0.f, 0.f, 0.f, 0.f);
            if (rp >= 0) {
                const int jab = (rp / NQ) * NQ + sjj[p];
                const float4 a  = *(const float4*)(g_P + (size_t)rp  * D + c4);
                const float4 nb = *(const float4*)(g_P + (size_t)jab * D + c4);
                const float4 bv = *(const float4*)(b3 + c4);
                v.x = fmaxf(a.x - nb.x + bv.x, 0.f);
                v.y = fmaxf(a.y - nb.y + bv.y, 0.f);
                v.z = fmaxf(a.z - nb.z + bv.z, 0.f);
                v.w = fmaxf(a.w - nb.w + bv.w, 0.f);
            }
            *(float4*)(Xs + p * XSTR + c4) = v;
        }

        float C[8][4];
        mma_layer(Xs, Ws, W4, C, rg, cg, g, tig, t);
        __syncthreads();

        // dump features back into Xs (X no longer needed)
#pragma unroll
        for (int nt = 0; nt < 8; nt++) {
            const int col = cg * 64 + nt * 8 + (tig << 1);
            const int p0 = rg * 16 + g, p1 = p0 + 8;
            *(float2*)(Xs + p0 * XSTR + col) = make_float2(C[nt][0], C[nt][1]);
            *(float2*)(Xs + p1 * XSTR + col) = make_float2(C[nt][2], C[nt][3]);
        }
        __syncthreads();

        // segmented max over consecutive same-row pairs, one atomic per run
        {
            int curRow = -1; float curMax = 0.f;
            for (int p = 0; p < GROUP; p++) {
                const int rp = spr[p];
                if (rp < 0) break;
                const float v = Xs[p * XSTR + t] + bias4;
                if (rp != curRow) {
                    if (curRow >= 0) atomicMaxFloat(&g_cur[(size_t)curRow * D + t], curMax);
                    curRow = rp; curMax = v;
                } else {
                    curMax = fmaxf(curMax, v);
                }
            }
            if (curRow >= 0) atomicMaxFloat(&g_cur[(size_t)curRow * D + t], curMax);
        }
        __syncthreads();
    }
}

// ---------------- K4b: out = tgt + relu(cur@W5+b5) for active rows ----------------
__global__ __launch_bounds__(256, 3) void k_out_gemv(
    const float* __restrict__ tgt,
    const float* __restrict__ W5, const float* __restrict__ b5,
    float* __restrict__ out)
{
    extern __shared__ float sm[];
    float* Xs = sm;
    float* Ws = sm + GROUP * XSTR;
    __shared__ int srow[GROUP];

    const int t = threadIdx.x;
    const int w = t >> 5, lane = t & 31;
    const int rg = w & 1, cg = w >> 1;
    const int g = lane >> 2, tig = lane & 3;
    const int nact = g_nout;

    for (int g0 = blockIdx.x * GROUP; g0 < nact; g0 += gridDim.x * GROUP) {
        if (t < GROUP) srow[t] = (g0 + t < nact) ? g_outrows[g0 + t] : -1;
        __syncthreads();

#pragma unroll
        for (int i = 0; i < 8; i++) {
            const int idx = t + (i << 8);
            const int r = idx >> 6, c4 = (idx & 63) << 2;
            const int rr = srow[r];
            const float4 v = (rr >= 0) ? *(const float4*)(g_cur + (size_t)rr * D + c4)
                                       : make_float4(0.f, 0.f, 0.f, 0.f);
            *(float4*)(Xs + r * XSTR + c4) = v;
        }

        float C[8][4];
        mma_layer(Xs, Ws, W5, C, rg, cg, g, tig, t);

#pragma unroll
        for (int nt = 0; nt < 8; nt++) {
            const int col = cg * 64 + nt * 8 + (tig << 1);
            const float2 bb = *(const float2*)(b5 + col);
            const int r0 = rg * 16 + g, r1 = r0 + 8;
            const int rw0 = srow[r0], rw1 = srow[r1];
            if (rw0 >= 0) {
                const float2 tg = *(const float2*)(tgt + (size_t)rw0 * D + col);
                *(float2*)(out + (size_t)rw0 * D + col) =
                    make_float2(tg.x + fmaxf(C[nt][0] + bb.x, 0.f),
                                tg.y + fmaxf(C[nt][1] + bb.y, 0.f));
            }
            if (rw1 >= 0) {
                const float2 tg = *(const float2*)(tgt + (size_t)rw1 * D + col);
                *(float2*)(out + (size_t)rw1 * D + col) =
                    make_float2(tg.x + fmaxf(C[nt][2] + bb.x, 0.f),
                                tg.y + fmaxf(C[nt][3] + bb.y, 0.f));
            }
        }
        __syncthreads();
    }
}

// ---------------- launch ----------------
extern "C" void kernel_launch(void* const* d_in, const int* in_sizes, int n_in,
                              void* d_out, int out_size) {
    const float* tgt  = (const float*)d_in[0];
    const float* seed = (const float*)d_in[1];
    const float* pred = (const float*)d_in[2];
    const float* W1 = (const float*)d_in[3];  const float* b1 = (const float*)d_in[4];
    const float* W2 = (const float*)d_in[5];  const float* b2 = (const float*)d_in[6];
    const float* g2 = (const float*)d_in[7];  const float* be2 = (const float*)d_in[8];
    const float* W3 = (const float*)d_in[9];  const float* b3 = (const float*)d_in[10];
    const float* W4 = (const float*)d_in[11]; const float* b4 = (const float*)d_in[12];
    const float* W5 = (const float*)d_in[13]; const float* b5 = (const float*)d_in[14];

    float* out = (float*)d_out;                 // cur_tgt: 8*1000*256 floats
    float* out_mask = out + (size_t)NROWS * D;  // attn_mask: 8*1000*1000 floats (0/1)

    cudaFuncSetAttribute(k_idtoken, cudaFuncAttributeMaxDynamicSharedMemorySize, SMEM_MMA);
    cudaFuncSetAttribute(k_feat,    cudaFuncAttributeMaxDynamicSharedMemorySize, SMEM_MMA);
    cudaFuncSetAttribute(k_out_gemv,cudaFuncAttributeMaxDynamicSharedMemorySize, SMEM_MMA);

    k_reset<<<(NROWS + 255) / 256, 256>>>();
    k_mask_sel<<<NROWS / MROWS, 256>>>(pred, seed, tgt, b5, out, out_mask);
    k_compact<<<(NROWS + 255) / 256, 256>>>();
    k_idtoken<<<GRID_MMA, 256, SMEM_MMA>>>(tgt, W1, b1, W2, b2, g2, be2, W3);
    k_feat<<<GRID_MMA, 256, SMEM_MMA>>>(b3, W4, b4);
    k_out_gemv<<<GRID_MMA, 256, SMEM_MMA>>>(tgt, W5, b5, out);
}

// round 9
// speedup vs baseline: 1.3803x; 1.3803x over previous
#include <cuda_runtime.h>
#include <math_constants.h>
#include <cstdint>

#define BS 8
#define NQ 1000
#define D 256
#define NROWS (BS * NQ)
#define TOPK 10
#define MAX_PAIRS (NROWS * TOPK)
#define MROWS 10      // rows per block in mask kernel
#define GROUP 32      // rows/pairs per group in MMA kernels
#define XSTR 260      // floats per X row in shared (unsplit, 256 + 4 pad)
#define WSTR 520      // floats per Ws k-row in shared ((hi,lo)x256 + 8 pad)
#define KC 16         // k-chunk (16 k-values per stage)
#define NCHUNK (D / KC)
#define WBUF (KC * WSTR)                 // floats per W buffer
#define GRID_MMA 296
#define SMEM_MMA ((GROUP * XSTR + 2 * WBUF) * 4)   // 99,840 bytes

// ---------------- scratch (no allocations allowed) ----------------
__device__ float g_P[NROWS * D];        // P = id_token @ W3 (active rows only)
__device__ float g_cur[NROWS * D];      // running max of masked features
__device__ float g_Wsp[5 * 256 * 512];  // pre-split (hi,lo) weights, 512-stride rows
__device__ int   g_pairs[MAX_PAIRS * 2];
__device__ int   g_pair_count;
__device__ int   g_flag[NROWS];
__device__ int   g_idrows[NROWS];
__device__ int   g_nid;
__device__ int   g_outrows[NROWS];
__device__ int   g_nout;

__global__ void k_reset() {
    const int i = blockIdx.x * 256 + threadIdx.x;
    if (i < NROWS) g_flag[i] = 0;
    if (i == 0) { g_pair_count = 0; g_nid = 0; g_nout = 0; }
}

__device__ __forceinline__ void atomicMaxFloat(float* addr, float v) {
    if (v >= 0.0f) atomicMax((int*)addr, __float_as_int(v));
    else           atomicMin((unsigned int*)addr, __float_as_uint(v));
}

// ---------------- tf32 split helpers ----------------
__device__ __forceinline__ void split_tf32(float x, float& hi, float& lo) {
    asm("cvt.rna.tf32.f32 %0, %1;" : "=f"(hi) : "f"(x));
    lo = x - hi;   // exact
}

// ---------------- cp.async helpers ----------------
__device__ __forceinline__ uint32_t smem_u32(const void* p) {
    return (uint32_t)__cvta_generic_to_shared(p);
}
__device__ __forceinline__ void cp16(uint32_t dst, const void* src) {
    asm volatile("cp.async.cg.shared.global [%0], [%1], 16;" :: "r"(dst), "l"(src));
}
__device__ __forceinline__ void cp_commit() {
    asm volatile("cp.async.commit_group;");
}
__device__ __forceinline__ void cp_wait0() {
    asm volatile("cp.async.wait_group 0;");
}

// ---------------- prep: split weights into (hi,lo) global layout ----------------
__global__ __launch_bounds__(256) void k_split_w(
    const float* __restrict__ W1, const float* __restrict__ W2,
    const float* __restrict__ W3, const float* __restrict__ W4,
    const float* __restrict__ W5)
{
    const int idx = blockIdx.x * 256 + threadIdx.x;   // over 5*65536
    if (idx >= 5 * 65536) return;
    const int w = idx >> 16, rem = idx & 65535;
    const float* Wt[5] = {W1, W2, W3, W4, W5};
    const float v = Wt[w][rem];
    float hi, lo; split_tf32(v, hi, lo);
    const int k = rem >> 8, n = rem & 255;
    float* dst = g_Wsp + ((size_t)(w * 256 + k) << 9) + (n << 1);
    dst[0] = hi; dst[1] = lo;
}

__device__ __forceinline__ void mma_tf32(float c[4],
    uint32_t a0, uint32_t a1, uint32_t a2, uint32_t a3,
    uint32_t b0, uint32_t b1)
{
    asm volatile(
        "mma.sync.aligned.m16n8k8.row.col.f32.tf32.tf32.f32 "
        "{%0,%1,%2,%3}, {%4,%5,%6,%7}, {%8,%9}, {%0,%1,%2,%3};"
        : "+f"(c[0]), "+f"(c[1]), "+f"(c[2]), "+f"(c[3])
        : "r"(a0), "r"(a1), "r"(a2), "r"(a3), "r"(b0), "r"(b1));
}

// stage one 16-k chunk of pre-split W into shared buffer via cp.async
__device__ __forceinline__ void stage_w(float* Wbuf, const float* __restrict__ Wsp,
                                        int kc, int t)
{
#pragma unroll
    for (int i = 0; i < 8; i++) {
        const int idx = t + (i << 8);        // 0..2047 16B segments
        const int row = idx >> 7;            // 0..15
        const int seg = idx & 127;           // 0..127 (x16B = 2048B row)
        cp16(smem_u32(Wbuf + row * WSTR + (seg << 2)),
             Wsp + (((size_t)(kc * KC + row)) << 9) + (seg << 2));
    }
    cp_commit();
}

// Core: C[8][4] = Xs(32 x D, unsplit) @ W (pre-split global), 3xTF32.
// Warp (rg,cg): rows rg*16..+15, cols cg*64..+63. Double-buffered cp.async staging.
__device__ __forceinline__ void mma_layer(
    const float* Xs, float* Ws, const float* __restrict__ Wsp,
    float C[8][4], int rg, int cg, int g, int tig, int t)
{
#pragma unroll
    for (int nt = 0; nt < 8; nt++)
#pragma unroll
        for (int i = 0; i < 4; i++) C[nt][i] = 0.0f;

    const int row0 = rg * 16 + g;

    stage_w(Ws, Wsp, 0, t);
    for (int kc = 0; kc < NCHUNK; kc++) {
        cp_wait0();
        __syncthreads();     // staged data visible; all warps done with other buffer
        if (kc + 1 < NCHUNK) stage_w(Ws + ((kc + 1) & 1) * WBUF, Wsp, kc + 1, t);
        const float* Wb = Ws + (kc & 1) * WBUF;
#pragma unroll
        for (int ks = 0; ks < KC; ks += 8) {
            const int kk = kc * KC + ks + tig;
            const float a0f = Xs[row0 * XSTR + kk];
            const float a1f = Xs[(row0 + 8) * XSTR + kk];
            const float a2f = Xs[row0 * XSTR + kk + 4];
            const float a3f = Xs[(row0 + 8) * XSTR + kk + 4];
            float a0h,a0l,a1h,a1l,a2h,a2l,a3h,a3l;
            split_tf32(a0f,a0h,a0l); split_tf32(a1f,a1h,a1l);
            split_tf32(a2f,a2h,a2l); split_tf32(a3f,a3h,a3l);
            const uint32_t A0h=__float_as_uint(a0h), A0l=__float_as_uint(a0l);
            const uint32_t A1h=__float_as_uint(a1h), A1l=__float_as_uint(a1l);
            const uint32_t A2h=__float_as_uint(a2h), A2l=__float_as_uint(a2l);
            const uint32_t A3h=__float_as_uint(a3h), A3l=__float_as_uint(a3l);
#pragma unroll
            for (int nt = 0; nt < 8; nt++) {
                const int col = cg * 64 + nt * 8 + g;
                const float2 b0 = *(const float2*)(Wb + (ks + tig) * WSTR + (col << 1));
                const float2 b1 = *(const float2*)(Wb + (ks + tig + 4) * WSTR + (col << 1));
                const uint32_t B0h=__float_as_uint(b0.x), B0l=__float_as_uint(b0.y);
                const uint32_t B1h=__float_as_uint(b1.x), B1l=__float_as_uint(b1.y);
                mma_tf32(C[nt], A0h,A1h,A2h,A3h, B0h, B1h);
                mma_tf32(C[nt], A0h,A1h,A2h,A3h, B0l, B1l);
                mma_tf32(C[nt], A0l,A1l,A2l,A3l, B0h, B1h);
            }
        }
        __syncthreads();     // all warps done reading this buffer before restage
    }
}

// ---------------- K2: IoU mask + selection + cur-init + base output ----------------
__global__ __launch_bounds__(256) void k_mask_sel(
    const float* __restrict__ pred, const float* __restrict__ seed,
    const float* __restrict__ tgt,  const float* __restrict__ b5,
    float* __restrict__ out, float* __restrict__ out_mask)
{
    const int base = blockIdx.x * MROWS;
    const int b = base / NQ;
    const int t = threadIdx.x;

    __shared__ float4 s_box[NQ];
    __shared__ float  s_seed[NQ];
    __shared__ int    s_cnt, s_m;
    __shared__ float  sval[256];
    __shared__ int    sidx[256];

    const float rb5 = fmaxf(b5[t], 0.0f);

    for (int j = t; j < NQ; j += 256) {
        s_box[j]  = ((const float4*)pred)[b * NQ + j];
        s_seed[j] = seed[b * NQ + j];
    }
    __syncthreads();

    for (int r = 0; r < MROWS; r++) {
        const int row = base + r;
        const int li  = row - b * NQ;
        if (t == 0) s_cnt = 0;
        __syncthreads();

        const float4 pb = s_box[li];
        const float bx1 = __fsub_rn(pb.x, __fmul_rn(0.5f, pb.z));
        const float by1 = __fsub_rn(pb.y, __fmul_rn(0.5f, pb.w));
        const float bx2 = __fadd_rn(pb.x, __fmul_rn(0.5f, pb.z));
        const float by2 = __fadd_rn(pb.y, __fmul_rn(0.5f, pb.w));
        const float ai  = __fmul_rn(__fsub_rn(bx2, bx1), __fsub_rn(by2, by1));
        const bool negi = (s_seed[li] == 0.0f);

        for (int j = t; j < NQ; j += 256) {
            const float4 q = s_box[j];
            const float qx1 = __fsub_rn(q.x, __fmul_rn(0.5f, q.z));
            const float qy1 = __fsub_rn(q.y, __fmul_rn(0.5f, q.w));
            const float qx2 = __fadd_rn(q.x, __fmul_rn(0.5f, q.z));
            const float qy2 = __fadd_rn(q.y, __fmul_rn(0.5f, q.w));
            const float aj  = __fmul_rn(__fsub_rn(qx2, qx1), __fsub_rn(qy2, qy1));
            const float w = fmaxf(__fsub_rn(fminf(bx2, qx2), fmaxf(bx1, qx1)), 0.0f);
            const float h = fmaxf(__fsub_rn(fminf(by2, qy2), fmaxf(by1, qy1)), 0.0f);
            const float inter = __fmul_rn(w, h);
            const float uni = __fsub_rn(__fadd_rn(ai, aj), inter);
            const float iou = __fdiv_rn(inter, uni);
            const bool attn = (iou >= 0.5f);
            out_mask[(size_t)row * NQ + j] = attn ? 1.0f : 0.0f;
            if (attn && negi && (s_seed[j] != 0.0f)) {
                int p = atomicAdd(&s_cnt, 1);
                if (p < 256) { sval[p] = iou; sidx[p] = j; }
            }
        }
        __syncthreads();

        if (t == 0) {
            int cnt = min(s_cnt, 256);
            int m;
            int sel[TOPK];
            if (cnt <= TOPK) {
                m = cnt;
                for (int qq = 0; qq < cnt; qq++) sel[qq] = sidx[qq];
            } else {
                m = TOPK;
                for (int rr = 0; rr < TOPK; rr++) {
                    float best = -1.0f; int bj = 0x7fffffff; int bp = -1;
                    for (int p = 0; p < cnt; p++) {
                        float v = sval[p]; int j = sidx[p];
                        if (v > best || (v == best && j < bj)) { best = v; bj = j; bp = p; }
                    }
                    sel[rr] = bj;
                    sval[bp] = -1.0f;
                }
            }
            s_m = m;
            if (m > 0) {
                int pbase = atomicAdd(&g_pair_count, m);
                for (int qq = 0; qq < m; qq++) {
                    g_pairs[2 * (pbase + qq)]     = row;
                    g_pairs[2 * (pbase + qq) + 1] = sel[qq];
                    g_flag[b * NQ + sel[qq]] = 1;
                }
                g_flag[row] = 1;
                int op = atomicAdd(&g_nout, 1);
                g_outrows[op] = row;
            }
        }
        __syncthreads();
        const int m = s_m;
        if (m == 0) {
            const float neg = 1.0f - s_seed[li];
            out[(size_t)row * D + t] = tgt[(size_t)row * D + t] + rb5 * neg;
        } else {
            g_cur[(size_t)row * D + t] = (m < TOPK) ? 0.0f : -CUDART_INF_F;
        }
    }
}

// ---------------- compaction of id-rows ----------------
__global__ void k_compact() {
    const int i = blockIdx.x * 256 + threadIdx.x;
    if (i < NROWS && g_flag[i]) {
        int p = atomicAdd(&g_nid, 1);
        g_idrows[p] = i;
    }
}

// ---------------- K3: P = (LN(relu(tgt@W1+b1)@W2+b2)*g2+be2) @ W3 ----------------
__global__ __launch_bounds__(256, 2) void k_idtoken(
    const float* __restrict__ tgt,
    const float* __restrict__ b1, const float* __restrict__ b2,
    const float* __restrict__ g2, const float* __restrict__ be2)
{
    extern __shared__ float sm[];
    float* Xs = sm;                       // GROUP * XSTR (unsplit)
    float* Ws = sm + GROUP * XSTR;        // 2 * WBUF (split pairs)
    __shared__ int   srow[GROUP];
    __shared__ float s_mean[GROUP], s_rstd[GROUP];

    const int t = threadIdx.x;
    const int w = t >> 5, lane = t & 31;
    const int rg = w & 1, cg = w >> 1;
    const int g = lane >> 2, tig = lane & 3;
    const int nact = g_nid;

    const float gv = g2[t], bev = be2[t];
    const float* W1sp = g_Wsp;
    const float* W2sp = g_Wsp + (1 << 17);
    const float* W3sp = g_Wsp + (2 << 17);

    for (int g0 = blockIdx.x * GROUP; g0 < nact; g0 += gridDim.x * GROUP) {
        if (t < GROUP) srow[t] = (g0 + t < nact) ? g_idrows[g0 + t] : -1;
        __syncthreads();

        // stage X = tgt rows (unsplit)
#pragma unroll
        for (int i = 0; i < 8; i++) {
            const int idx = t + (i << 8);
            const int r = idx >> 6, c4 = (idx & 63) << 2;
            const int rr = srow[r];
            const float4 v = (rr >= 0) ? *(const float4*)(tgt + (size_t)rr * D + c4)
                                       : make_float4(0.f, 0.f, 0.f, 0.f);
            *(float4*)(Xs + r * XSTR + c4) = v;
        }

        float C[8][4];
        // layer 1
        mma_layer(Xs, Ws, W1sp, C, rg, cg, g, tig, t);
#pragma unroll
        for (int nt = 0; nt < 8; nt++) {
            const int col = cg * 64 + nt * 8 + (tig << 1);
            const float2 bb = *(const float2*)(b1 + col);
            const int r0 = rg * 16 + g, r1 = r0 + 8;
            *(float2*)(Xs + r0 * XSTR + col) =
                make_float2(fmaxf(C[nt][0] + bb.x, 0.f), fmaxf(C[nt][1] + bb.y, 0.f));
            *(float2*)(Xs + r1 * XSTR + col) =
                make_float2(fmaxf(C[nt][2] + bb.x, 0.f), fmaxf(C[nt][3] + bb.y, 0.f));
        }
        __syncthreads();

        // layer 2 (pre-LN z)
        mma_layer(Xs, Ws, W2sp, C, rg, cg, g, tig, t);
#pragma unroll
        for (int nt = 0; nt < 8; nt++) {
            const int col = cg * 64 + nt * 8 + (tig << 1);
            const float2 bb = *(const float2*)(b2 + col);
            const int r0 = rg * 16 + g, r1 = r0 + 8;
            *(float2*)(Xs + r0 * XSTR + col) = make_float2(C[nt][0] + bb.x, C[nt][1] + bb.y);
            *(float2*)(Xs + r1 * XSTR + col) = make_float2(C[nt][2] + bb.x, C[nt][3] + bb.y);
        }
        __syncthreads();

        // LN stats: warp w handles rows 4w..4w+3
        for (int rr = (w << 2); rr < (w << 2) + 4; rr++) {
            float s = 0.f, sq = 0.f;
            for (int c = lane; c < D; c += 32) {
                const float z = Xs[rr * XSTR + c];
                s += z; sq += z * z;
            }
#pragma unroll
            for (int off = 16; off > 0; off >>= 1) {
                s  += __shfl_down_sync(0xffffffff, s,  off);
                sq += __shfl_down_sync(0xffffffff, sq, off);
            }
            if (lane == 0) {
                const float m = s * (1.0f / D);
                s_mean[rr] = m;
                s_rstd[rr] = rsqrtf(sq * (1.0f / D) - m * m + 1e-5f);
            }
        }
        __syncthreads();

        // LN transform
#pragma unroll 4
        for (int r = 0; r < GROUP; r++) {
            const float z = Xs[r * XSTR + t];
            Xs[r * XSTR + t] = (z - s_mean[r]) * s_rstd[r] * gv + bev;
        }

        // layer 3: P = id @ W3
        mma_layer(Xs, Ws, W3sp, C, rg, cg, g, tig, t);
#pragma unroll
        for (int nt = 0; nt < 8; nt++) {
            const int col = cg * 64 + nt * 8 + (tig << 1);
            const int r0 = rg * 16 + g, r1 = r0 + 8;
            const int rw0 = srow[r0], rw1 = srow[r1];
            if (rw0 >= 0)
                *(float2*)(g_P + (size_t)rw0 * D + col) = make_float2(C[nt][0], C[nt][1]);
            if (rw1 >= 0)
                *(float2*)(g_P + (size_t)rw1 * D + col) = make_float2(C[nt][2], C[nt][3]);
        }
        __syncthreads();
    }
}

// ---------------- K4a: per-pair relu(P_i - P_j + b3) @ W4 + b4 -> seg-max + atomic ----------------
__global__ __launch_bounds__(256, 2) void k_feat(
    const float* __restrict__ b3, const float* __restrict__ b4)
{
    extern __shared__ float sm[];
    float* Xs = sm;
    float* Ws = sm + GROUP * XSTR;
    __shared__ int spr[GROUP], sjj[GROUP];

    const int t = threadIdx.x;
    const int w = t >> 5, lane = t & 31;
    const int rg = w & 1, cg = w >> 1;
    const int g = lane >> 2, tig = lane & 3;
    const int npairs = g_pair_count;

    const float bias4 = b4[t];
    const float* W4sp = g_Wsp + (3 << 17);

    for (int g0 = blockIdx.x * GROUP; g0 < npairs; g0 += gridDim.x * GROUP) {
        if (t < GROUP) {
            if (g0 + t < npairs) {
                spr[t] = g_pairs[2 * (g0 + t)];
                sjj[t] = g_pairs[2 * (g0 + t) + 1];
            } else spr[t] = -1;
        }
        __syncthreads();

        // stage X = relu(P_i - P_j + b3)
#pragma unroll
        for (int i = 0; i < 8; i++) {
            const int idx = t + (i << 8);
            const int p = idx >> 6, c4 = (idx & 63) << 2;
            const int rp = spr[p];
            float4 v = make_float4(0.f, 0.f, 0.f, 0.f);
            if (rp >= 0) {
                const int jab = (rp / NQ) * NQ + sjj[p];
                const float4 a  = *(const float4*)(g_P + (size_t)rp  * D + c4);
                const float4 nb = *(const float4*)(g_P + (size_t)jab * D + c4);
                const float4 bv = *(const float4*)(b3 + c4);
                v.x = fmaxf(a.x - nb.x + bv.x, 0.f);
                v.y = fmaxf(a.y - nb.y + bv.y, 0.f);
                v.z = fmaxf(a.z - nb.z + bv.z, 0.f);
                v.w = fmaxf(a.w - nb.w + bv.w, 0.f);
            }
            *(float4*)(Xs + p * XSTR + c4) = v;
        }

        float C[8][4];
        mma_layer(Xs, Ws, W4sp, C, rg, cg, g, tig, t);

        // dump features back into Xs
#pragma unroll
        for (int nt = 0; nt < 8; nt++) {
            const int col = cg * 64 + nt * 8 + (tig << 1);
            const int p0 = rg * 16 + g, p1 = p0 + 8;
            *(float2*)(Xs + p0 * XSTR + col) = make_float2(C[nt][0], C[nt][1]);
            *(float2*)(Xs + p1 * XSTR + col) = make_float2(C[nt][2], C[nt][3]);
        }
        __syncthreads();

        // segmented max over consecutive same-row pairs, one atomic per run
        {
            int curRow = -1; float curMax = 0.f;
            for (int p = 0; p < GROUP; p++) {
                const int rp = spr[p];
                if (rp < 0) break;
                const float v = Xs[p * XSTR + t] + bias4;
                if (rp != curRow) {
                    if (curRow >= 0) atomicMaxFloat(&g_cur[(size_t)curRow * D + t], curMax);
                    curRow = rp; curMax = v;
                } else {
                    curMax = fmaxf(curMax, v);
                }
            }
            if (curRow >= 0) atomicMaxFloat(&g_cur[(size_t)curRow * D + t], curMax);
        }
        __syncthreads();
    }
}

// ---------------- K4b: out = tgt + relu(cur@W5+b5) for active rows ----------------
__global__ __launch_bounds__(256, 2) void k_out_gemv(
    const float* __restrict__ tgt, const float* __restrict__ b5,
    float* __restrict__ out)
{
    extern __shared__ float sm[];
    float* Xs = sm;
    float* Ws = sm + GROUP * XSTR;
    __shared__ int srow[GROUP];

    const int t = threadIdx.x;
    const int w = t >> 5, lane = t & 31;
    const int rg = w & 1, cg = w >> 1;
    const int g = lane >> 2, tig = lane & 3;
    const int nact = g_nout;
    const float* W5sp = g_Wsp + (4 << 17);

    for (int g0 = blockIdx.x * GROUP; g0 < nact; g0 += gridDim.x * GROUP) {
        if (t < GROUP) srow[t] = (g0 + t < nact) ? g_outrows[g0 + t] : -1;
        __syncthreads();

#pragma unroll
        for (int i = 0; i < 8; i++) {
            const int idx = t + (i << 8);
            const int r = idx >> 6, c4 = (idx & 63) << 2;
            const int rr = srow[r];
            const float4 v = (rr >= 0) ? *(const float4*)(g_cur + (size_t)rr * D + c4)
                                       : make_float4(0.f, 0.f, 0.f, 0.f);
            *(float4*)(Xs + r * XSTR + c4) = v;
        }

        float C[8][4];
        mma_layer(Xs, Ws, W5sp, C, rg, cg, g, tig, t);

#pragma unroll
        for (int nt = 0; nt < 8; nt++) {
            const int col = cg * 64 + nt * 8 + (tig << 1);
            const float2 bb = *(const float2*)(b5 + col);
            const int r0 = rg * 16 + g, r1 = r0 + 8;
            const int rw0 = srow[r0], rw1 = srow[r1];
            if (rw0 >= 0) {
                const float2 tg = *(const float2*)(tgt + (size_t)rw0 * D + col);
                *(float2*)(out + (size_t)rw0 * D + col) =
                    make_float2(tg.x + fmaxf(C[nt][0] + bb.x, 0.f),
                                tg.y + fmaxf(C[nt][1] + bb.y, 0.f));
            }
            if (rw1 >= 0) {
                const float2 tg = *(const float2*)(tgt + (size_t)rw1 * D + col);
                *(float2*)(out + (size_t)rw1 * D + col) =
                    make_float2(tg.x + fmaxf(C[nt][2] + bb.x, 0.f),
                                tg.y + fmaxf(C[nt][3] + bb.y, 0.f));
            }
        }
        __syncthreads();
    }
}

// ---------------- launch ----------------
extern "C" void kernel_launch(void* const* d_in, const int* in_sizes, int n_in,
                              void* d_out, int out_size) {
    const float* tgt  = (const float*)d_in[0];
    const float* seed = (const float*)d_in[1];
    const float* pred = (const float*)d_in[2];
    const float* W1 = (const float*)d_in[3];  const float* b1 = (const float*)d_in[4];
    const float* W2 = (const float*)d_in[5];  const float* b2 = (const float*)d_in[6];
    const float* g2 = (const float*)d_in[7];  const float* be2 = (const float*)d_in[8];
    const float* W3 = (const float*)d_in[9];  const float* b3 = (const float*)d_in[10];
    const float* W4 = (const float*)d_in[11]; const float* b4 = (const float*)d_in[12];
    const float* W5 = (const float*)d_in[13]; const float* b5 = (const float*)d_in[14];

    float* out = (float*)d_out;                 // cur_tgt: 8*1000*256 floats
    float* out_mask = out + (size_t)NROWS * D;  // attn_mask: 8*1000*1000 floats

    cudaFuncSetAttribute(k_idtoken, cudaFuncAttributeMaxDynamicSharedMemorySize, SMEM_MMA);
    cudaFuncSetAttribute(k_feat,    cudaFuncAttributeMaxDynamicSharedMemorySize, SMEM_MMA);
    cudaFuncSetAttribute(k_out_gemv,cudaFuncAttributeMaxDynamicSharedMemorySize, SMEM_MMA);

    k_reset<<<(NROWS + 255) / 256, 256>>>();
    k_split_w<<<(5 * 65536 + 255) / 256, 256>>>(W1, W2, W3, W4, W5);
    k_mask_sel<<<NROWS / MROWS, 256>>>(pred, seed, tgt, b5, out, out_mask);
    k_compact<<<(NROWS + 255) / 256, 256>>>();
    k_idtoken<<<GRID_MMA, 256, SMEM_MMA>>>(tgt, b1, b2, g2, be2);
    k_feat<<<GRID_MMA, 256, SMEM_MMA>>>(b3, b4);
    k_out_gemv<<<GRID_MMA, 256, SMEM_MMA>>>(tgt, b5, out);
}